// round 13
// baseline (speedup 1.0000x reference)
#include <cuda_runtime.h>

// WinCorr: out[s=(i,j,k), d,h,w] = scale * sum_c fixed[c,d,h,w] * moving[c, d+i-1, h+j-1, w+k-1]
// fixed/moving (1,32,96,96,96) f32; out (1,27,96,96,96) f32; zero padding.
//
// Main kernel: w in [1,96) via odd-aligned w-pairs + packed f32x2 FMA.
// Edge kernel: w == 0 column (k=0 shifts are identically zero there).

#define CC   32
#define DD   96
#define HH   96
#define WW   96
#define HWSZ (HH * WW)
#define DHW  (DD * HWSZ)

#define RW     40               // smem row width in words (covers gw [G0, G0+40))
#define SM_H   18               // gh in [h0-1, h0+16]
#define ROWS   (3 * SM_H)       // 54
#define TILE_W (ROWS * RW)      // 2160 words
#define TILE_B (TILE_W * 4)     // 8640 bytes
#define NSTAGE 4
#define QPR    10
#define TOTOPS (ROWS * QPR)     // 540
#define NOPS   5                // ceil(540/128)
#define NTHR   128

typedef unsigned long long ull;

__device__ __forceinline__ void cp_async16(unsigned s, const void* g) {
    asm volatile("cp.async.cg.shared.global [%0], [%1], 16;\n" :: "r"(s), "l"(g));
}
__device__ __forceinline__ void cp_commit() {
    asm volatile("cp.async.commit_group;\n" ::: "memory");
}
__device__ __forceinline__ void cp_wait2() {
    asm volatile("cp.async.wait_group 2;\n" ::: "memory");
}
__device__ __forceinline__ ull pk2(float lo, float hi) {
    ull r;
    asm("mov.b64 %0, {%1, %2};" : "=l"(r) : "r"(__float_as_uint(lo)), "r"(__float_as_uint(hi)));
    return r;
}
__device__ __forceinline__ void fma2(ull& d, ull a, ull b) {
    asm("fma.rn.f32x2 %0, %1, %2, %0;" : "+l"(d) : "l"(a), "l"(b));
}
__device__ __forceinline__ float2 upk(ull a) {
    unsigned x, y;
    asm("mov.b64 {%0, %1}, %2;" : "=r"(x), "=r"(y) : "l"(a));
    return make_float2(__uint_as_float(x), __uint_as_float(y));
}

__global__ __launch_bounds__(NTHR, 3)
void wincorr_kernel(const float* __restrict__ fx,
                    const float* __restrict__ mv,
                    float* __restrict__ out)
{
    __shared__ float sm[NSTAGE * TILE_W];   // 34560 B

    const int tx  = threadIdx.x;
    const int ty  = threadIdx.y;            // warp 0..3
    const int tid = ty * 32 + tx;
    const int t   = tx & 15;                // w-pair index
    const int hp  = tx >> 4;                // h sub-pair

    const int h0 = blockIdx.y * 16;
    const int d  = blockIdx.z;
    const int G0 = 32 * blockIdx.x - 4;     // smem word 0 <-> gw = G0 (16B-aligned)
    const int wa = 32 * blockIdx.x + 1 + 2 * t;   // odd; outputs (wa, wa+1)
    const int hb = h0 + 4 * ty + 2 * hp;          // outputs (hb, hb+1)
    const bool p_w1 = (wa < 95);            // second w output valid (wa+1 <= 95)

    // pre-zero all stages once: OOB halo slots stay zero for the whole kernel
    for (int i = tid; i < NSTAGE * TILE_W; i += NTHR) sm[i] = 0.f;

    // ---- per-thread c-invariant cp.async descriptors ----
    int      srcB[NOPS];    // byte offset within a moving channel; -1 = skip
    unsigned db[NOPS];      // byte offset within a stage
    #pragma unroll
    for (int k = 0; k < NOPS; ++k) {
        int o  = tid + NTHR * k;
        int r  = o / QPR;                   // tile row 0..53
        int q  = o - r * QPR;               // chunk 0..9
        int dz = r / SM_H;
        int lh = r - dz * SM_H;
        int gd = d  + dz - 1;
        int gh = h0 + lh - 1;
        int gs = G0 + 4 * q;                // chunk start gw (16B-aligned)
        bool v = (o < TOTOPS) && ((unsigned)gd < DD) && ((unsigned)gh < HH)
                              && (gs >= 0) && (gs + 4 <= WW);
        srcB[k] = v ? (gd * HWSZ + gh * WW + gs) * 4 : -1;
        db[k]   = (unsigned)(r * (RW * 4) + q * 16);
    }

    __syncthreads();   // zeros visible before any cp.async lands

    const unsigned smb = (unsigned)__cvta_generic_to_shared(sm);
    const char* mvb = (const char*)mv;

    // ---- prologue: launch channels 0..2 ----
    #pragma unroll
    for (int c = 0; c < 3; ++c) {
        const unsigned sb = smb + (unsigned)(c & (NSTAGE - 1)) * TILE_B;
        const char* pb = mvb + (size_t)c * (DHW * 4);
        #pragma unroll
        for (int k = 0; k < NOPS; ++k)
            if (srcB[k] >= 0) cp_async16(sb + db[k], pb + srcB[k]);
        cp_commit();
    }

    const float* fp = fx + (size_t)d * HWSZ + (size_t)hb * WW + wa;
    float f00 = __ldg(fp);
    float f01 = p_w1 ? __ldg(fp + 1) : 0.f;
    float f10 = __ldg(fp + WW);
    float f11 = p_w1 ? __ldg(fp + WW + 1) : 0.f;

    ull acc2[54];                           // [lo*27 + dz*9 + jj*3 + kk] = {out(wa), out(wa+1)}
    #pragma unroll
    for (int s = 0; s < 54; ++s) acc2[s] = 0ull;

    #pragma unroll 4
    for (int c = 0; c < CC; ++c) {
        cp_wait2();        // group c complete (c+1, c+2 still in flight)
        __syncthreads();   // all warps see tile c AND are done reading stage (c-1)&3

        // safe now: launch channel c+3 into stage (c+3)&3 == (c-1)&3
        const int jt = c + 3;
        if (jt < CC) {
            const unsigned sb = smb + (unsigned)(jt & (NSTAGE - 1)) * TILE_B;
            const char* pb = mvb + (size_t)jt * (DHW * 4);
            #pragma unroll
            for (int k = 0; k < NOPS; ++k)
                if (srcB[k] >= 0) cp_async16(sb + db[k], pb + srcB[k]);
        }
        cp_commit();       // unconditional: uniform group count for wait_group 2

        const ull fp0 = pk2(f00, f01);
        const ull fp1 = pk2(f10, f11);
        if (c + 1 < CC) {
            const float* fn = fp + (size_t)(c + 1) * DHW;
            f00 = __ldg(fn);
            f01 = p_w1 ? __ldg(fn + 1) : 0.f;
            f10 = __ldg(fn + WW);
            f11 = p_w1 ? __ldg(fn + WW + 1) : 0.f;
        }

        // ---- 24 LDS.64 + 12 packs + 54 FFMA2 ----
        const float* stp = sm + (c & (NSTAGE - 1)) * TILE_W;
        #pragma unroll
        for (int dz = 0; dz < 3; ++dz) {
            #pragma unroll
            for (int yy = 0; yy < 4; ++yy) {             // gh = hb-1+yy
                const float2* rp = (const float2*)(stp
                    + (dz * SM_H + 4 * ty + 2 * hp + yy) * RW + 2 * t + 4);
                const float2 A = rp[0];                  // {m[wa-1], m[wa]}  (kappa=-1)
                const float2 C = rp[1];                  // {m[wa+1], m[wa+2]} (kappa=+1)
                const ull pm1 = pk2(A.x, A.y);
                const ull pp1 = pk2(C.x, C.y);
                const ull p00 = pk2(A.y, C.x);           // kappa=0
                if (yy <= 2) {
                    const int b = dz * 9 + yy * 3;
                    fma2(acc2[b + 0], fp0, pm1);
                    fma2(acc2[b + 1], fp0, p00);
                    fma2(acc2[b + 2], fp0, pp1);
                }
                if (yy >= 1) {
                    const int b = 27 + dz * 9 + (yy - 1) * 3;
                    fma2(acc2[b + 0], fp1, pm1);
                    fma2(acc2[b + 1], fp1, p00);
                    fma2(acc2[b + 2], fp1, pp1);
                }
            }
        }
    }

    const float scale = 0.17677669529663687f;   // 32^-0.5
    #pragma unroll
    for (int lo = 0; lo < 2; ++lo) {
        float* op = out + (size_t)d * HWSZ + (size_t)(hb + lo) * WW + wa;
        #pragma unroll
        for (int s = 0; s < 27; ++s) {
            const float2 v = upk(acc2[lo * 27 + s]);
            op[(size_t)s * DHW] = v.x * scale;
            if (p_w1) op[(size_t)s * DHW + 1] = v.y * scale;
        }
    }
}

// ---- edge kernel: the w == 0 column (k=0 -> moving gw=-1 -> exactly zero) ----
__global__ __launch_bounds__(128)
void wincorr_edge_kernel(const float* __restrict__ fx,
                         const float* __restrict__ mv,
                         float* __restrict__ out)
{
    const int h = blockIdx.x * 32 + threadIdx.x;
    const int d = blockIdx.y * 4 + threadIdx.y;

    float acc[18];
    #pragma unroll
    for (int s = 0; s < 18; ++s) acc[s] = 0.f;

    const float* fp = fx + (size_t)d * HWSZ + (size_t)h * WW;   // w = 0
    for (int c = 0; c < CC; ++c) {
        const float f = __ldg(fp + (size_t)c * DHW);
        #pragma unroll
        for (int i = 0; i < 3; ++i) {
            const int gd = d + i - 1;
            #pragma unroll
            for (int j = 0; j < 3; ++j) {
                const int gh = h + j - 1;
                float m0 = 0.f, m1 = 0.f;
                if ((unsigned)gd < DD && (unsigned)gh < HH) {
                    const float* mp = mv + (size_t)c * DHW + (size_t)gd * HWSZ + (size_t)gh * WW;
                    m0 = __ldg(mp);        // gw = 0  (k=1)
                    m1 = __ldg(mp + 1);    // gw = 1  (k=2)
                }
                acc[(i * 3 + j) * 2 + 0] += f * m0;
                acc[(i * 3 + j) * 2 + 1] += f * m1;
            }
        }
    }

    const float scale = 0.17677669529663687f;
    float* op = out + (size_t)d * HWSZ + (size_t)h * WW;        // w = 0
    #pragma unroll
    for (int i = 0; i < 3; ++i)
        #pragma unroll
        for (int j = 0; j < 3; ++j) {
            const int sb = i * 9 + j * 3;
            op[(size_t)(sb + 0) * DHW] = 0.f;
            op[(size_t)(sb + 1) * DHW] = acc[(i * 3 + j) * 2 + 0] * scale;
            op[(size_t)(sb + 2) * DHW] = acc[(i * 3 + j) * 2 + 1] * scale;
        }
}

extern "C" void kernel_launch(void* const* d_in, const int* in_sizes, int n_in,
                              void* d_out, int out_size)
{
    const float* fixed  = (const float*)d_in[0];
    const float* moving = (const float*)d_in[1];
    float* out = (float*)d_out;

    dim3 eblock(32, 4, 1);
    dim3 egrid(HH / 32, DD / 4, 1);         // 72 blocks, w = 0 column
    wincorr_edge_kernel<<<egrid, eblock>>>(fixed, moving, out);

    dim3 block(32, 4, 1);                   // 128 threads
    dim3 grid(3, 6, DD);                    // w-pairs cover w in [1, 96]
    wincorr_kernel<<<grid, block>>>(fixed, moving, out);
}

// round 14
// speedup vs baseline: 1.6178x; 1.6178x over previous
#include <cuda_runtime.h>

// WinCorr: out[s=(i,j,k), d,h,w] = scale * sum_c fixed[c,d,h,w] * moving[c, d+i-1, h+j-1, w+k-1]
// fixed/moving (1,32,96,96,96) f32; out (1,27,96,96,96) f32; zero padding.
//
// bx in {0,1,2}: main path, odd w-pairs cover w in [1,95] (+ wa=95 singleton).
// bx == 3     : edge path, the w==0 column (k=0 shifts are identically zero there).

#define CC   32
#define DD   96
#define HH   96
#define WW   96
#define HWSZ (HH * WW)
#define DHW  (DD * HWSZ)

#define RW     40               // smem row width words (gw in [G0, G0+40))
#define SM_H   18               // gh in [h0-1, h0+16]
#define ROWS   (3 * SM_H)       // 54
#define TILE_W (ROWS * RW)      // 2160 words
#define TILE_B (TILE_W * 4)     // 8640 bytes
#define NSTAGE 4
#define QPR    10
#define TOTOPS (ROWS * QPR)     // 540
#define NOPS   5                // ceil(540/128)
#define NTHR   128

__device__ __forceinline__ void cp_async16(unsigned s, const void* g) {
    asm volatile("cp.async.cg.shared.global [%0], [%1], 16;\n" :: "r"(s), "l"(g));
}
__device__ __forceinline__ void cp_commit() {
    asm volatile("cp.async.commit_group;\n" ::: "memory");
}
__device__ __forceinline__ void cp_wait2() {
    asm volatile("cp.async.wait_group 2;\n" ::: "memory");
}

__global__ __launch_bounds__(NTHR, 3)
void wincorr_kernel(const float* __restrict__ fx,
                    const float* __restrict__ mv,
                    float* __restrict__ out)
{
    __shared__ float sm[NSTAGE * TILE_W];   // 34560 B

    const float scale = 0.17677669529663687f;   // 32^-0.5
    const int d  = blockIdx.z;
    const int h0 = blockIdx.y * 16;

    // ================= edge path: w == 0 column =================
    if (blockIdx.x == 3) {
        if (threadIdx.y != 0) return;            // one warp per edge block
        const int lx = threadIdx.x;
        const int hl = lx & 15;                  // h within strip
        const int kk = lx >> 4;                  // 0 -> k=1 (gw 0), 1 -> k=2 (gw 1)
        const int h  = h0 + hl;

        float acc[9];
        #pragma unroll
        for (int s = 0; s < 9; ++s) acc[s] = 0.f;

        const float* fp = fx + (size_t)d * HWSZ + (size_t)h * WW;   // w = 0
        for (int c = 0; c < CC; ++c) {
            const float f = __ldg(fp + (size_t)c * DHW);
            #pragma unroll
            for (int i = 0; i < 3; ++i) {
                const int gd = d + i - 1;
                #pragma unroll
                for (int j = 0; j < 3; ++j) {
                    const int gh = h + j - 1;
                    float m = 0.f;
                    if ((unsigned)gd < DD && (unsigned)gh < HH)
                        m = __ldg(mv + (size_t)c * DHW + (size_t)gd * HWSZ
                                     + (size_t)gh * WW + kk);
                    acc[i * 3 + j] += f * m;
                }
            }
        }

        float* op = out + (size_t)d * HWSZ + (size_t)h * WW;        // w = 0
        #pragma unroll
        for (int i = 0; i < 3; ++i)
            #pragma unroll
            for (int j = 0; j < 3; ++j) {
                const int sb = i * 9 + j * 3;
                op[(size_t)(sb + 1 + kk) * DHW] = acc[i * 3 + j] * scale;
                if (kk == 0) op[(size_t)sb * DHW] = 0.f;            // k=0: gw=-1 -> 0
            }
        return;
    }

    // ================= main path =================
    const int tx  = threadIdx.x;
    const int ty  = threadIdx.y;            // warp 0..3
    const int tid = ty * 32 + tx;
    const int t   = tx & 15;                // w-pair index
    const int hp  = tx >> 4;                // h sub-pair

    const int G0 = 32 * blockIdx.x - 4;     // smem word 0 <-> gw = G0 (16B-aligned)
    const int wa = 32 * blockIdx.x + 1 + 2 * t;   // odd; outputs (wa, wa+1)
    const int hb = h0 + 4 * ty + 2 * hp;          // outputs (hb, hb+1)
    const bool p_w1 = (wa < 95);            // wa+1 <= 95 ?

    // pre-zero all stages once: OOB halo slots stay zero for the whole kernel
    for (int i = tid; i < NSTAGE * TILE_W; i += NTHR) sm[i] = 0.f;

    // ---- per-thread c-invariant cp.async descriptors ----
    int      srcB[NOPS];    // byte offset within a moving channel; -1 = skip
    unsigned db[NOPS];      // byte offset within a stage
    #pragma unroll
    for (int k = 0; k < NOPS; ++k) {
        int o  = tid + NTHR * k;
        int r  = o / QPR;
        int q  = o - r * QPR;
        int dz = r / SM_H;
        int lh = r - dz * SM_H;
        int gd = d  + dz - 1;
        int gh = h0 + lh - 1;
        int gs = G0 + 4 * q;
        bool v = (o < TOTOPS) && ((unsigned)gd < DD) && ((unsigned)gh < HH)
                              && (gs >= 0) && (gs + 4 <= WW);
        srcB[k] = v ? (gd * HWSZ + gh * WW + gs) * 4 : -1;
        db[k]   = (unsigned)(r * (RW * 4) + q * 16);
    }

    __syncthreads();   // zeros visible before any cp.async lands

    const unsigned smb = (unsigned)__cvta_generic_to_shared(sm);
    const char* mvb = (const char*)mv;

    // ---- prologue: launch channels 0..2 ----
    #pragma unroll
    for (int c = 0; c < 3; ++c) {
        const unsigned sb = smb + (unsigned)(c & (NSTAGE - 1)) * TILE_B;
        const char* pb = mvb + (size_t)c * (DHW * 4);
        #pragma unroll
        for (int k = 0; k < NOPS; ++k)
            if (srcB[k] >= 0) cp_async16(sb + db[k], pb + srcB[k]);
        cp_commit();
    }

    const float* fp = fx + (size_t)d * HWSZ + (size_t)hb * WW + wa;
    float f00 = __ldg(fp);
    float f01 = p_w1 ? __ldg(fp + 1) : 0.f;
    float f10 = __ldg(fp + WW);
    float f11 = p_w1 ? __ldg(fp + WW + 1) : 0.f;

    float a00[27], a01[27], a10[27], a11[27];   // [h-out][w-out][s]
    #pragma unroll
    for (int s = 0; s < 27; ++s) { a00[s] = 0.f; a01[s] = 0.f; a10[s] = 0.f; a11[s] = 0.f; }

    #pragma unroll 4
    for (int c = 0; c < CC; ++c) {
        cp_wait2();        // group c complete (c+1, c+2 still in flight)
        __syncthreads();   // all warps see tile c AND are done reading stage (c-1)&3

        // safe now: launch channel c+3 into stage (c+3)&3 == (c-1)&3
        const int jt = c + 3;
        if (jt < CC) {
            const unsigned sb = smb + (unsigned)(jt & (NSTAGE - 1)) * TILE_B;
            const char* pb = mvb + (size_t)jt * (DHW * 4);
            #pragma unroll
            for (int k = 0; k < NOPS; ++k)
                if (srcB[k] >= 0) cp_async16(sb + db[k], pb + srcB[k]);
        }
        cp_commit();       // unconditional: uniform group count for wait_group 2

        const float g00 = f00, g01 = f01, g10 = f10, g11 = f11;
        if (c + 1 < CC) {
            const float* fn = fp + (size_t)(c + 1) * DHW;
            f00 = __ldg(fn);
            f01 = p_w1 ? __ldg(fn + 1) : 0.f;
            f10 = __ldg(fn + WW);
            f11 = p_w1 ? __ldg(fn + WW + 1) : 0.f;
        }

        // ---- 24 LDS.64 + 108 scalar FFMA ----
        const float* stp = sm + (c & (NSTAGE - 1)) * TILE_W;
        #pragma unroll
        for (int dz = 0; dz < 3; ++dz) {
            #pragma unroll
            for (int yy = 0; yy < 4; ++yy) {             // gh = hb-1+yy
                const float2* rp = (const float2*)(stp
                    + (dz * SM_H + 4 * ty + 2 * hp + yy) * RW + 2 * t + 4);
                const float2 A = rp[0];                  // {m[wa-1], m[wa]}
                const float2 C = rp[1];                  // {m[wa+1], m[wa+2]}
                if (yy <= 2) {
                    const int b = dz * 9 + yy * 3;
                    a00[b + 0] += g00 * A.x;  a00[b + 1] += g00 * A.y;  a00[b + 2] += g00 * C.x;
                    a01[b + 0] += g01 * A.y;  a01[b + 1] += g01 * C.x;  a01[b + 2] += g01 * C.y;
                }
                if (yy >= 1) {
                    const int b = dz * 9 + (yy - 1) * 3;
                    a10[b + 0] += g10 * A.x;  a10[b + 1] += g10 * A.y;  a10[b + 2] += g10 * C.x;
                    a11[b + 0] += g11 * A.y;  a11[b + 1] += g11 * C.x;  a11[b + 2] += g11 * C.y;
                }
            }
        }
    }

    float* op0 = out + (size_t)d * HWSZ + (size_t)hb * WW + wa;
    float* op1 = op0 + WW;
    #pragma unroll
    for (int s = 0; s < 27; ++s) {
        op0[(size_t)s * DHW] = a00[s] * scale;
        op1[(size_t)s * DHW] = a10[s] * scale;
        if (p_w1) {
            op0[(size_t)s * DHW + 1] = a01[s] * scale;
            op1[(size_t)s * DHW + 1] = a11[s] * scale;
        }
    }
}

extern "C" void kernel_launch(void* const* d_in, const int* in_sizes, int n_in,
                              void* d_out, int out_size)
{
    const float* fixed  = (const float*)d_in[0];
    const float* moving = (const float*)d_in[1];
    float* out = (float*)d_out;

    dim3 block(32, 4, 1);                   // 128 threads
    dim3 grid(4, 6, DD);                    // bx 0..2 main, bx 3 edge (w=0)
    wincorr_kernel<<<grid, block>>>(fixed, moving, out);
}

// round 16
// speedup vs baseline: 2.3480x; 1.4513x over previous
#include <cuda_runtime.h>

// WinCorr: out[s=(i,j,k), d,h,w] = scale * sum_c fixed[c,d,h,w] * moving[c, d+i-1, h+j-1, w+k-1]
// fixed/moving (1,32,96,96,96) f32; out (1,27,96,96,96) f32; zero padding.
// R11 structure, 3 h-outputs/thread -> 4 blocks/SM (16 warps) for latency hiding.

#define CC   32
#define DD   96
#define HH   96
#define WW   96
#define HWSZ (HH * WW)
#define DHW  (DD * HWSZ)

#define WT   32
#define HT   12                // 4 warps x 3 h-rows
#define SM_D 3
#define SM_H (HT + 2)          // 14
#define ROWS (SM_D * SM_H)     // 42
#define RW   40                // row width words (160B; gw in [w0-4, w0+36))
#define TILE_W (ROWS * RW)     // 1680 words
#define TILE_B (TILE_W * 4)    // 6720 bytes
#define NSTAGE 4
#define QPR  10                // 16B chunks per row
#define TOTOPS (ROWS * QPR)    // 420
#define NOPS 4                 // ceil(420/128)
#define NTHR 128

__device__ __forceinline__ void cp_async16(unsigned s, const void* g) {
    asm volatile("cp.async.cg.shared.global [%0], [%1], 16;\n" :: "r"(s), "l"(g));
}
__device__ __forceinline__ void cp_commit() {
    asm volatile("cp.async.commit_group;\n" ::: "memory");
}
__device__ __forceinline__ void cp_wait2() {
    asm volatile("cp.async.wait_group 2;\n" ::: "memory");
}

__global__ __launch_bounds__(NTHR, 4)
void wincorr_kernel(const float* __restrict__ fx,
                    const float* __restrict__ mv,
                    float* __restrict__ out)
{
    __shared__ float sm[NSTAGE * TILE_W];   // 26880 B -> 4 blocks/SM

    const int tx  = threadIdx.x;            // lane -> w
    const int ty  = threadIdx.y;            // warp 0..3 -> 3-row h strip
    const int tid = ty * 32 + tx;

    const int w0 = blockIdx.x * WT;
    const int h0 = blockIdx.y * HT;
    const int d  = blockIdx.z;

    const int h = h0 + 3 * ty;              // outputs h..h+2
    const int w = w0 + tx;

    // pre-zero all stages once: OOB halo slots stay zero for the whole kernel
    for (int i = tid; i < NSTAGE * TILE_W; i += NTHR) sm[i] = 0.f;

    // ---- per-thread c-invariant cp.async descriptors ----
    int      srcB[NOPS];   // byte offset within a moving channel; -1 = skip
    unsigned db[NOPS];     // byte offset within a stage
    #pragma unroll
    for (int t = 0; t < NOPS; ++t) {
        int o  = tid + NTHR * t;
        int r  = o / QPR;                   // tile row 0..41
        int q  = o - r * QPR;               // chunk 0..9
        int dz = r / SM_H;
        int lh = r - dz * SM_H;
        int gd = d  + dz - 1;
        int gh = h0 + lh - 1;
        int gs = w0 - 4 + 4 * q;
        bool v = (o < TOTOPS) && ((unsigned)gd < DD) && ((unsigned)gh < HH)
                              && (gs >= 0) && (gs + 4 <= WW);
        srcB[t] = v ? (gd * HWSZ + gh * WW + gs) * 4 : -1;
        db[t]   = (unsigned)(r * (RW * 4) + q * 16);
    }

    __syncthreads();   // zeros visible before any cp.async lands

    const unsigned smb = (unsigned)__cvta_generic_to_shared(sm);
    const char* mvb = (const char*)mv;

    // ---- prologue: launch channels 0..2 ----
    #pragma unroll
    for (int c = 0; c < 3; ++c) {
        const unsigned sb = smb + (unsigned)(c & (NSTAGE - 1)) * TILE_B;
        const char* pb = mvb + (size_t)c * (DHW * 4);
        #pragma unroll
        for (int t = 0; t < NOPS; ++t)
            if (srcB[t] >= 0) cp_async16(sb + db[t], pb + srcB[t]);
        cp_commit();
    }

    const float* fp = fx + (size_t)d * HWSZ + (size_t)h * WW + w;
    float fc[3];
    fc[0] = __ldg(fp);
    fc[1] = __ldg(fp + WW);
    fc[2] = __ldg(fp + 2 * WW);

    float acc[81];                          // [lo][dz*9 + jj*3 + kk]
    #pragma unroll
    for (int s = 0; s < 81; ++s) acc[s] = 0.f;

    #pragma unroll 4
    for (int c = 0; c < CC; ++c) {
        cp_wait2();        // group c complete (c+1, c+2 still in flight)
        __syncthreads();   // ALL warps see tile c AND are done reading stage (c-1)&3

        // safe now: launch channel c+3 into stage (c+3)&3 == (c-1)&3
        const int jt = c + 3;
        if (jt < CC) {
            const unsigned sb = smb + (unsigned)(jt & (NSTAGE - 1)) * TILE_B;
            const char* pb = mvb + (size_t)jt * (DHW * 4);
            #pragma unroll
            for (int t = 0; t < NOPS; ++t)
                if (srcB[t] >= 0) cp_async16(sb + db[t], pb + srcB[t]);
        }
        cp_commit();       // unconditional: uniform group count for wait_group 2

        const float f0 = fc[0], f1 = fc[1], f2 = fc[2];
        if (c + 1 < CC) {
            const float* fn = fp + (size_t)(c + 1) * DHW;
            fc[0] = __ldg(fn);
            fc[1] = __ldg(fn + WW);
            fc[2] = __ldg(fn + 2 * WW);
        }

        // ---- 45 conflict-free LDS [R+imm] + 81 FFMA ----
        // rows yy=0..4 -> gh = h-1+yy ; output lo uses jj = yy-lo in [0,2]
        const float* base = sm + (c & (NSTAGE - 1)) * TILE_W + (3 * ty) * RW + tx + 3;
        #pragma unroll
        for (int dz = 0; dz < 3; ++dz) {
            #pragma unroll
            for (int yy = 0; yy < 5; ++yy) {
                #pragma unroll
                for (int kk = 0; kk < 3; ++kk) {
                    const float m = base[(dz * SM_H + yy) * RW + kk];
                    if (yy <= 2)            acc[0 * 27 + dz * 9 + (yy    ) * 3 + kk] += f0 * m;
                    if (yy >= 1 && yy <= 3) acc[1 * 27 + dz * 9 + (yy - 1) * 3 + kk] += f1 * m;
                    if (yy >= 2)            acc[2 * 27 + dz * 9 + (yy - 2) * 3 + kk] += f2 * m;
                }
            }
        }
    }

    const float scale = 0.17677669529663687f;   // 32^-0.5
    float* op = out + (size_t)d * HWSZ + (size_t)h * WW + w;
    #pragma unroll
    for (int s = 0; s < 27; ++s) {
        #pragma unroll
        for (int lo = 0; lo < 3; ++lo)
            op[(size_t)s * DHW + lo * WW] = acc[lo * 27 + s] * scale;
    }
}

extern "C" void kernel_launch(void* const* d_in, const int* in_sizes, int n_in,
                              void* d_out, int out_size)
{
    const float* fixed  = (const float*)d_in[0];
    const float* moving = (const float*)d_in[1];
    float* out = (float*)d_out;

    dim3 block(32, 4, 1);                    // 128 threads
    dim3 grid(WW / WT, HH / HT, DD);         // (3, 8, 96) = 2304 blocks
    wincorr_kernel<<<grid, block>>>(fixed, moving, out);
}